// round 3
// baseline (speedup 1.0000x reference)
#include <cuda_runtime.h>
#include <stdint.h>

#define SEQ    2048
#define BITS   256
#define HEADS  8
#define NBPN   12
#define MAXD   8
#define NT     512
#define GRID_MAIN 152

// Scratch (device globals -- no allocation allowed)
__device__ uint32_t       g_tok[SEQ * 8];        // packed token bits, 32B/row
__device__ unsigned short g_Ak[SEQ * 8];         // per-row key-address parts
__device__ unsigned short g_Aq[SEQ * 8];         // per-row query-address parts
__device__ unsigned char  g_tabB[HEADS * 4096];  // table as bytes
__device__ unsigned short g_Ar[(MAXD + 1) * HEADS];

// ---------------------------------------------------------------------------
// Precompute: pack tokens into bitmasks, build Aq/Ak per row, Ar per distance,
// and convert the 0/1 float table to bytes.
// ---------------------------------------------------------------------------
__global__ void pre_kernel(const int* __restrict__ tokens,
                           const int* __restrict__ head_idx,
                           const float* __restrict__ table) {
    int tid = blockIdx.x * blockDim.x + threadIdx.x;

    if (tid < HEADS * 4096)
        g_tabB[tid] = (table[tid] > 0.5f) ? (unsigned char)1 : (unsigned char)0;

    if (tid < (MAXD + 1) * HEADS) {
        int d = tid / HEADS, h = tid % HEADS;
        int ar = 0;
        for (int k = 0; k < NBPN; k++) {
            int idx = head_idx[h * NBPN + k];
            if (idx >= 2 * BITS) {
                int p = idx - 2 * BITS;
                if (p > 3) p = 3;
                ar |= ((d >> p) & 1) << k;
            }
        }
        g_Ar[d * HEADS + h] = (unsigned short)ar;
    }

    if (tid < SEQ) {
        uint32_t w[8];
        const int4* row = (const int4*)(tokens + tid * BITS);
        #pragma unroll
        for (int wd = 0; wd < 8; wd++) {
            uint32_t x = 0;
            #pragma unroll
            for (int q = 0; q < 8; q++) {
                int4 v = row[wd * 8 + q];
                x |= (uint32_t)(v.x & 1) << (q * 4 + 0);
                x |= (uint32_t)(v.y & 1) << (q * 4 + 1);
                x |= (uint32_t)(v.z & 1) << (q * 4 + 2);
                x |= (uint32_t)(v.w & 1) << (q * 4 + 3);
            }
            w[wd] = x;
            g_tok[tid * 8 + wd] = x;
        }
        for (int h = 0; h < HEADS; h++) {
            int aq = 0, ak = 0;
            for (int k = 0; k < NBPN; k++) {
                int idx = head_idx[h * NBPN + k];
                if (idx < BITS) {
                    aq |= (int)((w[idx >> 5] >> (idx & 31)) & 1u) << k;
                } else if (idx < 2 * BITS) {
                    int i2 = idx - BITS;
                    ak |= (int)((w[i2 >> 5] >> (i2 & 31)) & 1u) << k;
                }
            }
            g_Aq[tid * 8 + h] = (unsigned short)aq;
            g_Ak[tid * 8 + h] = (unsigned short)ak;
        }
    }
}

// ---------------------------------------------------------------------------
// Main: persistent CTAs, one row i at a time. Whole working set in SMEM.
// votes(i,j) = sum_h tableB[h][Aq[i,h]+Ak[j,h]+Ar[min(i-j,8),h]]
// attended -> XOR-accumulate token bitmask; argmax via packed int key.
// ---------------------------------------------------------------------------
__global__ __launch_bounds__(NT, 1)
void main_kernel(float* __restrict__ out) {
    extern __shared__ unsigned char smem[];
    unsigned char* sTab  = smem;                        // 32768 B
    uint4*         sAk4  = (uint4*)(smem + 32768);      // 32768 B (8 x u16 per row)
    uint32_t*      sTokW = (uint32_t*)(smem + 65536);   // 65536 B
    uint4*         sTok4 = (uint4*)sTokW;
    uint32_t*      sRed  = (uint32_t*)(smem + 131072);  // 16 warps x 10 words
    uint32_t*      sFin  = sRed + 160;                  // 16 words

    const int tid = threadIdx.x;

    // Stage working set into SMEM once per block
    {
        const uint4* g1 = (const uint4*)g_tabB;
        uint4* s1 = (uint4*)sTab;
        for (int x = tid; x < 2048; x += NT) s1[x] = g1[x];
        const uint4* g2 = (const uint4*)g_Ak;
        for (int x = tid; x < 2048; x += NT) sAk4[x] = g2[x];
        const uint4* g3 = (const uint4*)g_tok;
        for (int x = tid; x < 4096; x += NT) sTok4[x] = g3[x];
    }
    __syncthreads();

    const int lane = tid & 31, wid = tid >> 5;
    const int b0 = (int)blockIdx.x;

    for (int t = 0;; t++) {
        // alternating assignment balances the O(i) per-row cost
        int i = t * GRID_MAIN + ((t & 1) ? (GRID_MAIN - 1 - b0) : b0);
        if (i >= SEQ) break;

        int off[8];
        #pragma unroll
        for (int h = 0; h < 8; h++)
            off[h] = h * 4096 + (int)g_Aq[i * 8 + h] + (int)g_Ar[MAXD * HEADS + h];

        uint32_t a0 = 0, a1 = 0, a2 = 0, a3 = 0, a4 = 0, a5 = 0, a6 = 0, a7 = 0;
        int cnt = 0;
        int kmax = -1;

        for (int j = tid; j <= i; j += NT) {
            uint4 akv = sAk4[j];
            int o0 = off[0] + (int)(akv.x & 0xFFFFu);
            int o1 = off[1] + (int)(akv.x >> 16);
            int o2 = off[2] + (int)(akv.y & 0xFFFFu);
            int o3 = off[3] + (int)(akv.y >> 16);
            int o4 = off[4] + (int)(akv.z & 0xFFFFu);
            int o5 = off[5] + (int)(akv.z >> 16);
            int o6 = off[6] + (int)(akv.w & 0xFFFFu);
            int o7 = off[7] + (int)(akv.w >> 16);

            int d = i - j;
            if (d < MAXD) {  // rare near-diagonal fixup: swap Ar[8] -> Ar[d]
                o0 += (int)g_Ar[d * HEADS + 0] - (int)g_Ar[MAXD * HEADS + 0];
                o1 += (int)g_Ar[d * HEADS + 1] - (int)g_Ar[MAXD * HEADS + 1];
                o2 += (int)g_Ar[d * HEADS + 2] - (int)g_Ar[MAXD * HEADS + 2];
                o3 += (int)g_Ar[d * HEADS + 3] - (int)g_Ar[MAXD * HEADS + 3];
                o4 += (int)g_Ar[d * HEADS + 4] - (int)g_Ar[MAXD * HEADS + 4];
                o5 += (int)g_Ar[d * HEADS + 5] - (int)g_Ar[MAXD * HEADS + 5];
                o6 += (int)g_Ar[d * HEADS + 6] - (int)g_Ar[MAXD * HEADS + 6];
                o7 += (int)g_Ar[d * HEADS + 7] - (int)g_Ar[MAXD * HEADS + 7];
            }

            int v = (int)sTab[o0] + (int)sTab[o1] + (int)sTab[o2] + (int)sTab[o3] +
                    (int)sTab[o4] + (int)sTab[o5] + (int)sTab[o6] + (int)sTab[o7];

            if (v >= HEADS / 2) {
                cnt++;
                uint4 t0 = sTok4[2 * j];
                uint4 t1 = sTok4[2 * j + 1];
                a0 ^= t0.x; a1 ^= t0.y; a2 ^= t0.z; a3 ^= t0.w;
                a4 ^= t1.x; a5 ^= t1.y; a6 ^= t1.z; a7 ^= t1.w;
            }
            // argmax with ties -> smallest j, as one int max
            int key = (v << 12) | (2047 - j);
            kmax = max(kmax, key);
        }

        // warp reduction
        #pragma unroll
        for (int s = 16; s; s >>= 1) {
            a0 ^= __shfl_xor_sync(0xFFFFFFFFu, a0, s);
            a1 ^= __shfl_xor_sync(0xFFFFFFFFu, a1, s);
            a2 ^= __shfl_xor_sync(0xFFFFFFFFu, a2, s);
            a3 ^= __shfl_xor_sync(0xFFFFFFFFu, a3, s);
            a4 ^= __shfl_xor_sync(0xFFFFFFFFu, a4, s);
            a5 ^= __shfl_xor_sync(0xFFFFFFFFu, a5, s);
            a6 ^= __shfl_xor_sync(0xFFFFFFFFu, a6, s);
            a7 ^= __shfl_xor_sync(0xFFFFFFFFu, a7, s);
            cnt += __shfl_xor_sync(0xFFFFFFFFu, cnt, s);
            kmax = max(kmax, __shfl_xor_sync(0xFFFFFFFFu, kmax, s));
        }
        if (lane == 0) {
            uint32_t* p = sRed + wid * 10;
            p[0] = a0; p[1] = a1; p[2] = a2; p[3] = a3;
            p[4] = a4; p[5] = a5; p[6] = a6; p[7] = a7;
            p[8] = (uint32_t)cnt; p[9] = (uint32_t)kmax;
        }
        __syncthreads();
        if (tid < 10) {
            uint32_t x = sRed[tid];
            for (int q = 1; q < NT / 32; q++) {
                uint32_t y = sRed[q * 10 + tid];
                if (tid < 8)       x ^= y;
                else if (tid == 8) x += y;
                else               x = (uint32_t)max((int)x, (int)y);
            }
            sFin[tid] = x;
        }
        __syncthreads();

        if (tid < BITS) {
            uint32_t bitv;
            if (sFin[8] > 0) {
                bitv = (sFin[tid >> 5] >> (tid & 31)) & 1u;         // parity
            } else {
                int aj = 2047 - ((int)sFin[9] & 4095);              // argmax row
                bitv = (sTokW[aj * 8 + (tid >> 5)] >> (tid & 31)) & 1u;
            }
            out[i * BITS + tid] = (float)bitv;
        }
        __syncthreads();  // protect sRed/sFin before next row
    }
}

extern "C" void kernel_launch(void* const* d_in, const int* in_sizes, int n_in,
                              void* d_out, int out_size) {
    const int*   tokens   = (const int*)d_in[0];
    const int*   head_idx = (const int*)d_in[1];
    const float* table    = (const float*)d_in[2];
    float*       out      = (float*)d_out;

    const int SMEM_BYTES = 131072 + 176 * 4;
    cudaFuncSetAttribute(main_kernel,
                         cudaFuncAttributeMaxDynamicSharedMemorySize, SMEM_BYTES);

    pre_kernel<<<128, 256>>>(tokens, head_idx, table);
    main_kernel<<<GRID_MAIN, NT, SMEM_BYTES>>>(out);
}

// round 4
// speedup vs baseline: 2.4725x; 2.4725x over previous
#include <cuda_runtime.h>
#include <stdint.h>

#define SEQ    2048
#define BITS   256
#define HEADS  8
#define NBPN   12
#define MAXD   8
#define NT     512
#define GRID_MAIN 152

// Scratch (device globals -- no allocation allowed)
__device__ uint32_t       g_tok[SEQ * 8];        // packed token bits, 32B/row
__device__ unsigned short g_Ak[SEQ * 8];         // per-row key-address parts
__device__ unsigned short g_Aq[SEQ * 8];         // per-row query-address parts
__device__ unsigned char  g_tabB[HEADS * 4096];  // table as bytes
__device__ short          g_Ar[(MAXD + 1) * HEADS];

// ---------------------------------------------------------------------------
// Precompute (warp-per-row): ballot-pack token bits, build Aq/Ak per row,
// Ar per distance, table floats -> bytes.
// ---------------------------------------------------------------------------
__global__ void pre_kernel(const int* __restrict__ tokens,
                           const int* __restrict__ head_idx,
                           const float* __restrict__ table) {
    int tid = blockIdx.x * blockDim.x + threadIdx.x;

    if (tid < HEADS * 4096)
        g_tabB[tid] = (table[tid] > 0.5f) ? (unsigned char)1 : (unsigned char)0;

    if (tid < (MAXD + 1) * HEADS) {
        int d = tid / HEADS, h = tid % HEADS;
        int ar = 0;
        for (int k = 0; k < NBPN; k++) {
            int idx = head_idx[h * NBPN + k];
            if (idx >= 2 * BITS) {
                int p = idx - 2 * BITS;
                if (p > 3) p = 3;
                ar |= ((d >> p) & 1) << k;
            }
        }
        g_Ar[d * HEADS + h] = (short)ar;
    }

    int row  = tid >> 5;
    int lane = tid & 31;
    if (row < SEQ) {
        uint32_t w[8];
        #pragma unroll
        for (int q = 0; q < 8; q++) {
            int v = tokens[row * BITS + q * 32 + lane];
            w[q] = __ballot_sync(0xFFFFFFFFu, v & 1);   // all lanes get the word
        }
        if (lane < 8) {
            g_tok[row * 8 + lane] = w[lane];
            int h = lane;
            int aq = 0, ak = 0;
            for (int k = 0; k < NBPN; k++) {
                int idx = head_idx[h * NBPN + k];
                if (idx < BITS) {
                    aq |= (int)((w[idx >> 5] >> (idx & 31)) & 1u) << k;
                } else if (idx < 2 * BITS) {
                    int i2 = idx - BITS;
                    ak |= (int)((w[i2 >> 5] >> (i2 & 31)) & 1u) << k;
                }
            }
            g_Aq[row * 8 + h] = (unsigned short)aq;
            g_Ak[row * 8 + h] = (unsigned short)ak;
        }
    }
}

// ---------------------------------------------------------------------------
// Main: persistent CTAs, ONE WARP PER ROW. Whole working set in SMEM.
// No block-level syncs in the hot path.
// ---------------------------------------------------------------------------
__global__ __launch_bounds__(NT, 1)
void main_kernel(float* __restrict__ out) {
    extern __shared__ unsigned char smem[];
    unsigned char* sTab   = smem;                      // 32768 B
    uint4*         sAk4   = (uint4*)(smem + 32768);    // 32768 B
    uint4*         sTokLo = (uint4*)(smem + 65536);    // 32768 B (words 0..3)
    uint4*         sTokHi = (uint4*)(smem + 98304);    // 32768 B (words 4..7)
    int*           sArD   = (int*)(smem + 131072);     // 72 ints: Ar[d]-Ar[8]

    const int tid = threadIdx.x;

    // Stage working set into SMEM once per block
    {
        const uint4* g1 = (const uint4*)g_tabB;
        uint4* s1 = (uint4*)sTab;
        for (int x = tid; x < 2048; x += NT) s1[x] = g1[x];
        const uint4* g2 = (const uint4*)g_Ak;
        for (int x = tid; x < 2048; x += NT) sAk4[x] = g2[x];
        const uint4* g3 = (const uint4*)g_tok;
        for (int x = tid; x < 4096; x += NT) {
            uint4 v = g3[x];
            if (x & 1) sTokHi[x >> 1] = v; else sTokLo[x >> 1] = v;
        }
        if (tid < (MAXD + 1) * HEADS)
            sArD[tid] = (int)g_Ar[tid] - (int)g_Ar[MAXD * HEADS + (tid & 7)];
    }
    __syncthreads();

    const int lane = tid & 31, wid = tid >> 5;
    const int i = wid * GRID_MAIN + (int)blockIdx.x;   // one row per warp
    if (i >= SEQ) return;

    int off0 = 0 * 4096 + (int)g_Aq[i * 8 + 0] + (int)g_Ar[MAXD * HEADS + 0];
    int off1 = 1 * 4096 + (int)g_Aq[i * 8 + 1] + (int)g_Ar[MAXD * HEADS + 1];
    int off2 = 2 * 4096 + (int)g_Aq[i * 8 + 2] + (int)g_Ar[MAXD * HEADS + 2];
    int off3 = 3 * 4096 + (int)g_Aq[i * 8 + 3] + (int)g_Ar[MAXD * HEADS + 3];
    int off4 = 4 * 4096 + (int)g_Aq[i * 8 + 4] + (int)g_Ar[MAXD * HEADS + 4];
    int off5 = 5 * 4096 + (int)g_Aq[i * 8 + 5] + (int)g_Ar[MAXD * HEADS + 5];
    int off6 = 6 * 4096 + (int)g_Aq[i * 8 + 6] + (int)g_Ar[MAXD * HEADS + 6];
    int off7 = 7 * 4096 + (int)g_Aq[i * 8 + 7] + (int)g_Ar[MAXD * HEADS + 7];

    uint32_t a0 = 0, a1 = 0, a2 = 0, a3 = 0, a4 = 0, a5 = 0, a6 = 0, a7 = 0;
    int cnt = 0;
    int kmax = -1;

    #pragma unroll 2
    for (int j = lane; j <= i; j += 32) {
        uint4 akv = sAk4[j];
        int o0 = off0 + (int)(akv.x & 0xFFFFu);
        int o1 = off1 + (int)(akv.x >> 16);
        int o2 = off2 + (int)(akv.y & 0xFFFFu);
        int o3 = off3 + (int)(akv.y >> 16);
        int o4 = off4 + (int)(akv.z & 0xFFFFu);
        int o5 = off5 + (int)(akv.z >> 16);
        int o6 = off6 + (int)(akv.w & 0xFFFFu);
        int o7 = off7 + (int)(akv.w >> 16);

        int d = i - j;
        if (d < MAXD) {   // only possible in the final iteration of the loop
            o0 += sArD[d * 8 + 0];
            o1 += sArD[d * 8 + 1];
            o2 += sArD[d * 8 + 2];
            o3 += sArD[d * 8 + 3];
            o4 += sArD[d * 8 + 4];
            o5 += sArD[d * 8 + 5];
            o6 += sArD[d * 8 + 6];
            o7 += sArD[d * 8 + 7];
        }

        int v = (int)sTab[o0] + (int)sTab[o1] + (int)sTab[o2] + (int)sTab[o3] +
                (int)sTab[o4] + (int)sTab[o5] + (int)sTab[o6] + (int)sTab[o7];

        if (v >= HEADS / 2) {
            cnt++;
            uint4 t0 = sTokLo[j];
            uint4 t1 = sTokHi[j];
            a0 ^= t0.x; a1 ^= t0.y; a2 ^= t0.z; a3 ^= t0.w;
            a4 ^= t1.x; a5 ^= t1.y; a6 ^= t1.z; a7 ^= t1.w;
        }
        kmax = max(kmax, (v << 12) | (2047 - j));   // ties -> smallest j
    }

    // warp butterfly: every lane ends with the full row result
    #pragma unroll
    for (int s = 16; s; s >>= 1) {
        a0 ^= __shfl_xor_sync(0xFFFFFFFFu, a0, s);
        a1 ^= __shfl_xor_sync(0xFFFFFFFFu, a1, s);
        a2 ^= __shfl_xor_sync(0xFFFFFFFFu, a2, s);
        a3 ^= __shfl_xor_sync(0xFFFFFFFFu, a3, s);
        a4 ^= __shfl_xor_sync(0xFFFFFFFFu, a4, s);
        a5 ^= __shfl_xor_sync(0xFFFFFFFFu, a5, s);
        a6 ^= __shfl_xor_sync(0xFFFFFFFFu, a6, s);
        a7 ^= __shfl_xor_sync(0xFFFFFFFFu, a7, s);
        cnt  += __shfl_xor_sync(0xFFFFFFFFu, cnt, s);
        kmax  = max(kmax, __shfl_xor_sync(0xFFFFFFFFu, kmax, s));
    }

    // each lane writes 8 consecutive output bits of row i
    int widx = lane >> 2;                 // which 32-bit word (0..7)
    uint32_t w;
    if (cnt > 0) {
        w = a0;
        if (widx == 1) w = a1;
        if (widx == 2) w = a2;
        if (widx == 3) w = a3;
        if (widx == 4) w = a4;
        if (widx == 5) w = a5;
        if (widx == 6) w = a6;
        if (widx == 7) w = a7;
    } else {
        int aj = 2047 - (kmax & 4095);
        const uint32_t* lo = (const uint32_t*)sTokLo;
        const uint32_t* hi = (const uint32_t*)sTokHi;
        w = (widx < 4) ? lo[aj * 4 + widx] : hi[aj * 4 + (widx - 4)];
    }
    int sh = (lane & 3) * 8;
    float4* o = (float4*)(out + i * BITS + lane * 8);
    o[0] = make_float4((float)((w >> (sh + 0)) & 1u), (float)((w >> (sh + 1)) & 1u),
                       (float)((w >> (sh + 2)) & 1u), (float)((w >> (sh + 3)) & 1u));
    o[1] = make_float4((float)((w >> (sh + 4)) & 1u), (float)((w >> (sh + 5)) & 1u),
                       (float)((w >> (sh + 6)) & 1u), (float)((w >> (sh + 7)) & 1u));
}

extern "C" void kernel_launch(void* const* d_in, const int* in_sizes, int n_in,
                              void* d_out, int out_size) {
    const int*   tokens   = (const int*)d_in[0];
    const int*   head_idx = (const int*)d_in[1];
    const float* table    = (const float*)d_in[2];
    float*       out      = (float*)d_out;

    const int SMEM_BYTES = 131072 + 512;
    cudaFuncSetAttribute(main_kernel,
                         cudaFuncAttributeMaxDynamicSharedMemorySize, SMEM_BYTES);

    pre_kernel<<<(SEQ * 32 + 255) / 256, 256>>>(tokens, head_idx, table);
    main_kernel<<<GRID_MAIN, NT, SMEM_BYTES>>>(out);
}